// round 7
// baseline (speedup 1.0000x reference)
#include <cuda_runtime.h>

#define BB 4
#define LL 512
#define NTYPE 20
#define HH 6
#define DKK 10
#define DMM 60
#define EDD 59

// device scratch (no allocation allowed)
__device__ float g_q[BB*LL*DMM];        // q pre-scaled by 1/sqrt(DK)
__device__ float g_k[BB*LL*DMM];
__device__ float g_v[BB*LL*DMM];
__device__ float g_va3[BB*3*3*LL*DKK];  // scrambled folded tables
__device__ float g_vg3[BB*3*3*LL*DKK];
__device__ float g_p[BB*HH*LL*LL];      // masked UNnormalized exp rows [b][h][q][j]
__device__ float g_scale[BB*HH*LL];     // 1/rowsum
__device__ float g_vmu[BB*LL*DMM];      // normalized (p@v), head-concat per (b,q)

// ---------------- K1: prep (16 rows/block, smem-staged weights) ----------------
__global__ __launch_bounds__(256)
void prep_kernel(const float* __restrict__ ev, const float* __restrict__ embed_w,
                 const float* __restrict__ q_w, const float* __restrict__ q_b,
                 const float* __restrict__ k_w, const float* __restrict__ k_b,
                 const float* __restrict__ v_w, const float* __restrict__ v_b,
                 const float* __restrict__ alpha_w, const float* __restrict__ gamma_w)
{
    __shared__ float wq[3600], wk[3600], wv[3600];   // transposed [n][m]
    __shared__ float wa[300], wg[300];               // transposed [c][k]
    __shared__ float feat[16][DMM];
    __shared__ float vr[16][DMM];
    __shared__ int   tys[16];
    int t = threadIdx.x;
    int row0 = blockIdx.x * 16;
    int b = row0 >> 9, j0 = row0 & (LL-1);
    const float* e = ev + (size_t)b*(LL+1)*2;

    if (t < 16) {
        int j = j0 + t;
        float tprev = (j > 0) ? e[(j-1)*2] : 0.0f;
        feat[t][0] = e[j*2] - tprev;
        tys[t] = (int)e[j*2 + 1];
    }
    for (int i = t; i < 3600; i += 256) {
        int m = i / 60, n = i - m*60;
        wq[n*60+m] = q_w[i]; wk[n*60+m] = k_w[i]; wv[n*60+m] = v_w[i];
    }
    for (int i = t; i < 300; i += 256) {
        int k = i / 30, c = i - k*30;
        wa[c*10 + k] = alpha_w[i]; wg[c*10 + k] = gamma_w[i];
    }
    __syncthreads();
    for (int i = t; i < 16*EDD; i += 256) {
        int r = i / EDD, m = i - r*EDD;
        feat[r][1+m] = embed_w[m*NTYPE + tys[r]];
    }
    __syncthreads();
    for (int i = t; i < 960; i += 256) {
        int r = i / 60, m = i - r*60;
        float sq = q_b[m], sk = k_b[m], sv = v_b[m];
        #pragma unroll
        for (int n = 0; n < 60; n++) {
            float fv = feat[r][n];
            sq += fv * wq[n*60+m];
            sk += fv * wk[n*60+m];
            sv += fv * wv[n*60+m];
        }
        int gi = (row0 + r)*60 + m;
        g_q[gi] = sq * 0.31622776601683794f;
        g_k[gi] = sk;
        g_v[gi] = sv;
        vr[r][m] = sv;
    }
    __syncthreads();
    for (int i = t; i < 1440; i += 256) {
        int r = i / 90, rem = i - r*90;
        int h = rem / 30, e3 = (rem / 10) % 3, k = rem % 10;
        int j = j0 + r;
        int g = (j + 2*e3) % 3;
        float sa = 0.f, sg = 0.f;
        #pragma unroll
        for (int d = 0; d < 10; d++) {
            sa += vr[r][h*10 + d]      * wa[(g*10+d)*10 + k];
            sg += vr[r][30 + h*10 + d] * wg[(g*10+d)*10 + k];
        }
        int idx = (((b*3 + h)*3 + e3)*LL + j)*DKK + k;
        g_va3[idx] = sa;
        g_vg3[idx] = sg;
    }
}

// ---------------- K2: attention rows (exp, rowsum, p@v) ----------------
// block = (b, h, qc 0..7); q-stripe: q = 8*li + qc, li=0..63. warp handles q-pairs.
__global__ __launch_bounds__(256)
void attn_kernel()
{
    int bx = blockIdx.x;
    int qc = bx & 7, bh = bx >> 3;
    int h = bh % 6, b = bh / 6;
    __shared__ float ks[LL*DKK], vs_[LL*DKK], qs[64*DKK];
    int t = threadIdx.x;
    const float* kg = g_k + (size_t)(b*LL)*DMM + h*DKK;
    const float* vg = g_v + (size_t)(b*LL)*DMM + h*DKK;
    const float* qg = g_q + (size_t)(b*LL)*DMM + h*DKK;
    for (int i = t; i < 2560; i += 256) {
        int j = i / 5, d2 = i - j*5;
        ((float2*)ks)[j*5 + d2]  = *(const float2*)(kg + (size_t)j*DMM + d2*2);
        ((float2*)vs_)[j*5 + d2] = *(const float2*)(vg + (size_t)j*DMM + d2*2);
    }
    for (int i = t; i < 320; i += 256) {
        int li = i / 5, d2 = i - li*5;
        int q = 8*li + qc;
        ((float2*)qs)[li*5 + d2] = *(const float2*)(qg + (size_t)q*DMM + d2*2);
    }
    __syncthreads();
    int w = t >> 5, lane = t & 31;
    const unsigned FULL = 0xffffffffu;
    for (int p = 0; p < 4; p++) {
        int li0 = w*8 + p*2, li1 = li0 + 1;
        int q0 = 8*li0 + qc, q1 = 8*li1 + qc;   // q1 = q0 + 8
        float q0r[10], q1r[10];
        #pragma unroll
        for (int d = 0; d < 10; d++) { q0r[d] = qs[li0*10+d]; q1r[d] = qs[li1*10+d]; }
        float sum0 = 0.f, sum1 = 0.f;
        float vm0[10], vm1[10];
        #pragma unroll
        for (int d = 0; d < 10; d++) { vm0[d] = 0.f; vm1[d] = 0.f; }
        int row0 = (b*HH + h)*LL + q0;
        int row1 = row0 + 8;
        float* p0 = g_p + (size_t)row0*LL;
        float* p1 = g_p + (size_t)row1*LL;
        int j = lane;
        for (; j <= q1; j += 32) {
            float kd[10], vd[10];
            #pragma unroll
            for (int d2 = 0; d2 < 5; d2++) {
                float2 kk = ((float2*)ks)[j*5 + d2];
                float2 vv = ((float2*)vs_)[j*5 + d2];
                kd[2*d2] = kk.x; kd[2*d2+1] = kk.y;
                vd[2*d2] = vv.x; vd[2*d2+1] = vv.y;
            }
            float s1 = 0.f;
            #pragma unroll
            for (int d = 0; d < 10; d++) s1 += q1r[d]*kd[d];
            float e1 = __expf(s1);
            sum1 += e1;
            #pragma unroll
            for (int d = 0; d < 10; d++) vm1[d] += e1*vd[d];
            float e0 = 0.f;
            if (j <= q0) {
                float s0 = 0.f;
                #pragma unroll
                for (int d = 0; d < 10; d++) s0 += q0r[d]*kd[d];
                e0 = __expf(s0);
                sum0 += e0;
                #pragma unroll
                for (int d = 0; d < 10; d++) vm0[d] += e0*vd[d];
            }
            p0[j] = e0;
            p1[j] = e1;
        }
        for (; j < LL; j += 32) { p0[j] = 0.f; p1[j] = 0.f; }
        #pragma unroll
        for (int o = 16; o > 0; o >>= 1) {
            sum0 += __shfl_xor_sync(FULL, sum0, o);
            sum1 += __shfl_xor_sync(FULL, sum1, o);
            #pragma unroll
            for (int d = 0; d < 10; d++) {
                vm0[d] += __shfl_xor_sync(FULL, vm0[d], o);
                vm1[d] += __shfl_xor_sync(FULL, vm1[d], o);
            }
        }
        if (lane == 0) {
            float i0 = 1.0f / sum0, i1 = 1.0f / sum1;
            g_scale[row0] = i0;
            g_scale[row1] = i1;
            float* o0 = g_vmu + ((size_t)(b*LL + q0))*DMM + h*DKK;
            float* o1 = g_vmu + ((size_t)(b*LL + q1))*DMM + h*DKK;
            #pragma unroll
            for (int d = 0; d < 10; d++) { o0[d] = vm0[d]*i0; o1[d] = vm1[d]*i1; }
        }
    }
}

// ---------------- K3: v_mu final sigmoid GEMV ----------------
__global__ __launch_bounds__(256)
void vmu_final(const float* __restrict__ mu_w, const float* __restrict__ mu_b,
               float* __restrict__ out)
{
    int idx = blockIdx.x*256 + threadIdx.x;
    if (idx >= BB*LL*DKK) return;
    int row = idx / DKK, k = idx - row*DKK;
    float s = mu_b[k];
    const float* pre = g_vmu + (size_t)row*DMM;
    #pragma unroll
    for (int m = 0; m < DMM; m++) s += pre[m] * __ldg(mu_w + k*DMM + m);
    out[idx] = 1.0f / (1.0f + __expf(-s));
}

__device__ __forceinline__ float softplus_f(float x) {
    return fmaxf(x, 0.f) + __logf(1.f + __expf(-fabsf(x)));
}

// ---------------- K4: fused softplus output ----------------
// block g in [0,128) per batch handles ips {2g, 2g+1, 510-2g, 511-2g}
// (constant total valid work per block). Scalar-stride inner loop: warp
// lanes hold CONSECUTIVE f => table LDGs span ~2-3 lines instead of ~12.
__global__ __launch_bounds__(256)
void big_kernel(const float* __restrict__ alpha_b,
                const float* __restrict__ gamma_b,
                float* __restrict__ out)
{
    int bx = blockIdx.x;                 // 512 blocks
    int b = bx >> 7, g = bx & 127;
    int ips[4];
    ips[0] = 2*g; ips[1] = 2*g + 1; ips[2] = 510 - 2*g; ips[3] = 511 - 2*g;
    __shared__ float pa[12*LL], pg[12*LL];    // 48KB
    __shared__ float ab[DKK], gb[DKK];
    __shared__ int   rowAs[12], rowGs[12];
    __shared__ float scAs[12], scGs[12];
    int t = threadIdx.x;
    if (t < DKK) { ab[t] = alpha_b[t]; gb[t] = gamma_b[t]; }
    if (t < 12) {
        int ipi = t / 3, e = t - ipi*3;
        int R = 3*ips[ipi] + e;
        int hA = R >> 9, q = R & (LL-1);
        int ra = (b*HH + hA)*LL + q;
        int rg = (b*HH + 3 + hA)*LL + q;
        rowAs[t] = ra; scAs[t] = g_scale[ra];
        rowGs[t] = rg; scGs[t] = g_scale[rg];
    }
    __syncthreads();
    for (int idx = t; idx < 12*128; idx += 256) {
        int r = idx >> 7, j4 = idx & 127;
        float4 va = ((const float4*)(g_p + (size_t)rowAs[r]*LL))[j4];
        float4 vg = ((const float4*)(g_p + (size_t)rowGs[r]*LL))[j4];
        float sa = scAs[r], sg = scGs[r];
        va.x *= sa; va.y *= sa; va.z *= sa; va.w *= sa;
        vg.x *= sg; vg.y *= sg; vg.z *= sg; vg.w *= sg;
        ((float4*)pa)[idx] = va;
        ((float4*)pg)[idx] = vg;
    }
    __syncthreads();

    #pragma unroll
    for (int ipi = 0; ipi < 4; ipi++) {
        int ip = ips[ipi];
        size_t baseA = (size_t)BB*LL*DKK + ((size_t)(b*LL + ip))*(LL*DKK);
        size_t baseG = baseA + (size_t)BB*LL*LL*DKK;
        int tabb[3];
        #pragma unroll
        for (int e = 0; e < 3; e++) {
            int R = 3*ip + e;
            int hh = R >> 9;
            tabb[e] = ((b*3 + hh)*3 + e) * (LL*DKK);
        }
        int pbase = ipi * 1536;
        int nvalid = (ip + 1) * DKK;
        for (int f = t; f < LL*DKK; f += 256) {
            int jp = f / 10, k = f - jp*10;
            float A = 0.f, G = 0.f;
            if (f < nvalid) {
                A = ab[k]; G = gb[k];
                int u = 3*jp;
                #pragma unroll
                for (int m = 0; m < 3; m++, u++) {
                    int e = u >> 9, j = u & (LL-1);
                    int ti = tabb[e] + j*10 + k;
                    A += pa[pbase + u] * g_va3[ti];
                    G += pg[pbase + u] * g_vg3[ti];
                }
                A = softplus_f(A);
                G = 0.1f * softplus_f(10.0f * G);
            }
            out[baseA + f] = A;
            out[baseG + f] = G;
        }
    }
}

extern "C" void kernel_launch(void* const* d_in, const int* in_sizes, int n_in,
                              void* d_out, int out_size) {
    const float* ev      = (const float*)d_in[0];
    // d_in[1] = src_mask (deterministic tril) — recomputed as j<=i
    const float* embed_w = (const float*)d_in[2];
    const float* q_w     = (const float*)d_in[3];
    const float* q_b     = (const float*)d_in[4];
    const float* k_w     = (const float*)d_in[5];
    const float* k_b     = (const float*)d_in[6];
    const float* v_w     = (const float*)d_in[7];
    const float* v_b     = (const float*)d_in[8];
    const float* alpha_w = (const float*)d_in[9];
    const float* alpha_b = (const float*)d_in[10];
    const float* gamma_w = (const float*)d_in[11];
    const float* gamma_b = (const float*)d_in[12];
    const float* mu_w    = (const float*)d_in[13];
    const float* mu_b    = (const float*)d_in[14];
    float* out = (float*)d_out;

    prep_kernel<<<128, 256>>>(ev, embed_w, q_w, q_b, k_w, k_b, v_w, v_b, alpha_w, gamma_w);
    attn_kernel<<<BB*HH*8, 256>>>();
    vmu_final<<<(BB*LL*DKK + 255)/256, 256>>>(mu_w, mu_b, out);
    big_kernel<<<512, 256>>>(alpha_b, gamma_b, out);
}

// round 9
// speedup vs baseline: 1.5946x; 1.5946x over previous
#include <cuda_runtime.h>

#define BB 4
#define LL 512
#define NTYPE 20
#define HH 6
#define DKK 10
#define DMM 60
#define EDD 59

// device scratch (no allocation allowed)
__device__ float g_q[BB*LL*DMM];        // q pre-scaled by 1/sqrt(DK)
__device__ float g_k[BB*LL*DMM];
__device__ float g_v[BB*LL*DMM];
__device__ __align__(16) float g_va3[BB*3*3*LL*DKK];  // scrambled folded tables
__device__ __align__(16) float g_vg3[BB*3*3*LL*DKK];
__device__ __align__(16) float g_p[BB*HH*LL*LL];      // masked UNnormalized exp rows
__device__ float g_scale[BB*HH*LL];     // 1/rowsum
__device__ float g_vmu[BB*LL*DMM];      // normalized (p@v), head-concat per (b,q)

// ---------------- K1: prep (16 rows/block, smem-staged weights) ----------------
__global__ __launch_bounds__(256)
void prep_kernel(const float* __restrict__ ev, const float* __restrict__ embed_w,
                 const float* __restrict__ q_w, const float* __restrict__ q_b,
                 const float* __restrict__ k_w, const float* __restrict__ k_b,
                 const float* __restrict__ v_w, const float* __restrict__ v_b,
                 const float* __restrict__ alpha_w, const float* __restrict__ gamma_w)
{
    __shared__ float wq[3600], wk[3600], wv[3600];   // transposed [n][m]
    __shared__ float wa[300], wg[300];               // transposed [c][k]
    __shared__ float feat[16][DMM];
    __shared__ float vr[16][DMM];
    __shared__ int   tys[16];
    int t = threadIdx.x;
    int row0 = blockIdx.x * 16;
    int b = row0 >> 9, j0 = row0 & (LL-1);
    const float* e = ev + (size_t)b*(LL+1)*2;

    if (t < 16) {
        int j = j0 + t;
        float tprev = (j > 0) ? e[(j-1)*2] : 0.0f;
        feat[t][0] = e[j*2] - tprev;
        tys[t] = (int)e[j*2 + 1];
    }
    for (int i = t; i < 3600; i += 256) {
        int m = i / 60, n = i - m*60;
        wq[n*60+m] = q_w[i]; wk[n*60+m] = k_w[i]; wv[n*60+m] = v_w[i];
    }
    for (int i = t; i < 300; i += 256) {
        int k = i / 30, c = i - k*30;
        wa[c*10 + k] = alpha_w[i]; wg[c*10 + k] = gamma_w[i];
    }
    __syncthreads();
    for (int i = t; i < 16*EDD; i += 256) {
        int r = i / EDD, m = i - r*EDD;
        feat[r][1+m] = embed_w[m*NTYPE + tys[r]];
    }
    __syncthreads();
    for (int i = t; i < 960; i += 256) {
        int r = i / 60, m = i - r*60;
        float sq = q_b[m], sk = k_b[m], sv = v_b[m];
        #pragma unroll
        for (int n = 0; n < 60; n++) {
            float fv = feat[r][n];
            sq += fv * wq[n*60+m];
            sk += fv * wk[n*60+m];
            sv += fv * wv[n*60+m];
        }
        int gi = (row0 + r)*60 + m;
        g_q[gi] = sq * 0.31622776601683794f;
        g_k[gi] = sk;
        g_v[gi] = sv;
        vr[r][m] = sv;
    }
    __syncthreads();
    for (int i = t; i < 1440; i += 256) {
        int r = i / 90, rem = i - r*90;
        int h = rem / 30, e3 = (rem / 10) % 3, k = rem % 10;
        int j = j0 + r;
        int g = (j + 2*e3) % 3;
        float sa = 0.f, sg = 0.f;
        #pragma unroll
        for (int d = 0; d < 10; d++) {
            sa += vr[r][h*10 + d]      * wa[(g*10+d)*10 + k];
            sg += vr[r][30 + h*10 + d] * wg[(g*10+d)*10 + k];
        }
        int idx = (((b*3 + h)*3 + e3)*LL + j)*DKK + k;
        g_va3[idx] = sa;
        g_vg3[idx] = sg;
    }
}

// ---------------- K2: attention rows (exp, rowsum, p@v) ----------------
__global__ __launch_bounds__(256)
void attn_kernel()
{
    int bx = blockIdx.x;
    int qc = bx & 7, bh = bx >> 3;
    int h = bh % 6, b = bh / 6;
    __shared__ float ks[LL*DKK], vs_[LL*DKK], qs[64*DKK];
    int t = threadIdx.x;
    const float* kg = g_k + (size_t)(b*LL)*DMM + h*DKK;
    const float* vg = g_v + (size_t)(b*LL)*DMM + h*DKK;
    const float* qg = g_q + (size_t)(b*LL)*DMM + h*DKK;
    for (int i = t; i < 2560; i += 256) {
        int j = i / 5, d2 = i - j*5;
        ((float2*)ks)[j*5 + d2]  = *(const float2*)(kg + (size_t)j*DMM + d2*2);
        ((float2*)vs_)[j*5 + d2] = *(const float2*)(vg + (size_t)j*DMM + d2*2);
    }
    for (int i = t; i < 320; i += 256) {
        int li = i / 5, d2 = i - li*5;
        int q = 8*li + qc;
        ((float2*)qs)[li*5 + d2] = *(const float2*)(qg + (size_t)q*DMM + d2*2);
    }
    __syncthreads();
    int w = t >> 5, lane = t & 31;
    const unsigned FULL = 0xffffffffu;
    for (int p = 0; p < 4; p++) {
        int li0 = w*8 + p*2, li1 = li0 + 1;
        int q0 = 8*li0 + qc, q1 = 8*li1 + qc;   // q1 = q0 + 8
        float q0r[10], q1r[10];
        #pragma unroll
        for (int d = 0; d < 10; d++) { q0r[d] = qs[li0*10+d]; q1r[d] = qs[li1*10+d]; }
        float sum0 = 0.f, sum1 = 0.f;
        float vm0[10], vm1[10];
        #pragma unroll
        for (int d = 0; d < 10; d++) { vm0[d] = 0.f; vm1[d] = 0.f; }
        int row0 = (b*HH + h)*LL + q0;
        int row1 = row0 + 8;
        float* p0 = g_p + (size_t)row0*LL;
        float* p1 = g_p + (size_t)row1*LL;
        int j = lane;
        for (; j <= q1; j += 32) {
            float kd[10], vd[10];
            #pragma unroll
            for (int d2 = 0; d2 < 5; d2++) {
                float2 kk = ((float2*)ks)[j*5 + d2];
                float2 vv = ((float2*)vs_)[j*5 + d2];
                kd[2*d2] = kk.x; kd[2*d2+1] = kk.y;
                vd[2*d2] = vv.x; vd[2*d2+1] = vv.y;
            }
            float s1 = 0.f;
            #pragma unroll
            for (int d = 0; d < 10; d++) s1 += q1r[d]*kd[d];
            float e1 = __expf(s1);
            sum1 += e1;
            #pragma unroll
            for (int d = 0; d < 10; d++) vm1[d] += e1*vd[d];
            float e0 = 0.f;
            if (j <= q0) {
                float s0 = 0.f;
                #pragma unroll
                for (int d = 0; d < 10; d++) s0 += q0r[d]*kd[d];
                e0 = __expf(s0);
                sum0 += e0;
                #pragma unroll
                for (int d = 0; d < 10; d++) vm0[d] += e0*vd[d];
            }
            p0[j] = e0;
            p1[j] = e1;
        }
        for (; j < LL; j += 32) { p0[j] = 0.f; p1[j] = 0.f; }
        #pragma unroll
        for (int o = 16; o > 0; o >>= 1) {
            sum0 += __shfl_xor_sync(FULL, sum0, o);
            sum1 += __shfl_xor_sync(FULL, sum1, o);
            #pragma unroll
            for (int d = 0; d < 10; d++) {
                vm0[d] += __shfl_xor_sync(FULL, vm0[d], o);
                vm1[d] += __shfl_xor_sync(FULL, vm1[d], o);
            }
        }
        if (lane == 0) {
            float i0 = 1.0f / sum0, i1 = 1.0f / sum1;
            g_scale[row0] = i0;
            g_scale[row1] = i1;
            float* o0 = g_vmu + ((size_t)(b*LL + q0))*DMM + h*DKK;
            float* o1 = g_vmu + ((size_t)(b*LL + q1))*DMM + h*DKK;
            #pragma unroll
            for (int d = 0; d < 10; d++) { o0[d] = vm0[d]*i0; o1[d] = vm1[d]*i1; }
        }
    }
}

// ---------------- K3: v_mu final sigmoid GEMV ----------------
__global__ __launch_bounds__(256)
void vmu_final(const float* __restrict__ mu_w, const float* __restrict__ mu_b,
               float* __restrict__ out)
{
    int idx = blockIdx.x*256 + threadIdx.x;
    if (idx >= BB*LL*DKK) return;
    int row = idx / DKK, k = idx - row*DKK;
    float s = mu_b[k];
    const float* pre = g_vmu + (size_t)row*DMM;
    #pragma unroll
    for (int m = 0; m < DMM; m++) s += pre[m] * __ldg(mu_w + k*DMM + m);
    out[idx] = 1.0f / (1.0f + __expf(-s));
}

__device__ __forceinline__ float softplus_f(float x) {
    return fmaxf(x, 0.f) + __logf(1.f + __expf(-fabsf(x)));
}

// ---------------- K4: fused softplus output ----------------
// Valid/invalid regions SPLIT: compute loop runs only f < nvalid (no
// predicated dead issues); zero region is a pure float2-store loop.
// float2 over k-pairs halves index math + memory instruction count.
// Table address: (3b+h)*15360 + u*10 + k (e*5120 terms cancel).
__global__ __launch_bounds__(256)
void big_kernel(const float* __restrict__ alpha_b,
                const float* __restrict__ gamma_b,
                float* __restrict__ out)
{
    int bx = blockIdx.x;                 // 512 blocks
    int b = bx >> 7, g = bx & 127;
    int ips[4];
    ips[0] = 2*g; ips[1] = 2*g + 1; ips[2] = 510 - 2*g; ips[3] = 511 - 2*g;
    __shared__ float pa[12*LL], pg[12*LL];    // 48KB
    __shared__ float2 ab2[5], gb2[5];
    __shared__ int   rowAs[12], rowGs[12];
    __shared__ float scAs[12], scGs[12];
    int t = threadIdx.x;
    if (t < 5) {
        ab2[t] = make_float2(alpha_b[2*t], alpha_b[2*t+1]);
        gb2[t] = make_float2(gamma_b[2*t], gamma_b[2*t+1]);
    }
    if (t < 12) {
        int ipi = t / 3, e = t - ipi*3;
        int R = 3*ips[ipi] + e;
        int hA = R >> 9, q = R & (LL-1);
        int ra = (b*HH + hA)*LL + q;
        int rg = (b*HH + 3 + hA)*LL + q;
        rowAs[t] = ra; scAs[t] = g_scale[ra];
        rowGs[t] = rg; scGs[t] = g_scale[rg];
    }
    __syncthreads();
    for (int idx = t; idx < 12*128; idx += 256) {
        int r = idx >> 7, j4 = idx & 127;
        float4 va = ((const float4*)(g_p + (size_t)rowAs[r]*LL))[j4];
        float4 vg = ((const float4*)(g_p + (size_t)rowGs[r]*LL))[j4];
        float sa = scAs[r], sg = scGs[r];
        va.x *= sa; va.y *= sa; va.z *= sa; va.w *= sa;
        vg.x *= sg; vg.y *= sg; vg.z *= sg; vg.w *= sg;
        ((float4*)pa)[idx] = va;
        ((float4*)pg)[idx] = vg;
    }
    __syncthreads();

    int hbase = 3*b;
    #pragma unroll
    for (int ipi = 0; ipi < 4; ipi++) {
        int ip = ips[ipi];
        size_t baseA = (size_t)BB*LL*DKK + ((size_t)(b*LL + ip))*(LL*DKK);
        size_t baseG = baseA + (size_t)BB*LL*LL*DKK;
        int pbase = ipi * 1536;
        int nvalid2 = (ip + 1) * 5;      // float2 units per row (valid)
        int ip3 = 3*ip;
        // ---- compute region ----
        for (int f2 = t; f2 < nvalid2; f2 += 256) {
            int jp = f2 / 5;
            int k2 = f2 - jp*5;
            int kk = k2 + k2;
            int u = 3*jp;
            float2 A = ab2[k2], G = gb2[k2];
            int pb = pbase + u;
            #pragma unroll
            for (int m = 0; m < 3; m++) {
                int uu = u + m;
                int e = uu >> 9;
                int h = (ip3 + e) >> 9;
                int addr = (hbase + h)*15360 + uu*10 + kk;
                float2 Ta = *(const float2*)(g_va3 + addr);
                float2 Tg = *(const float2*)(g_vg3 + addr);
                float pA = pa[pb + m];
                float pG = pg[pb + m];
                A.x = fmaf(pA, Ta.x, A.x);
                A.y = fmaf(pA, Ta.y, A.y);
                G.x = fmaf(pG, Tg.x, G.x);
                G.y = fmaf(pG, Tg.y, G.y);
            }
            A.x = softplus_f(A.x);
            A.y = softplus_f(A.y);
            G.x = 0.1f * softplus_f(10.0f * G.x);
            G.y = 0.1f * softplus_f(10.0f * G.y);
            *(float2*)(out + baseA + 2*f2) = A;
            *(float2*)(out + baseG + 2*f2) = G;
        }
        // ---- zero region (masked j > i) ----
        float2 z2 = make_float2(0.f, 0.f);
        for (int f2 = nvalid2 + t; f2 < 2560; f2 += 256) {
            *(float2*)(out + baseA + 2*f2) = z2;
            *(float2*)(out + baseG + 2*f2) = z2;
        }
    }
}

extern "C" void kernel_launch(void* const* d_in, const int* in_sizes, int n_in,
                              void* d_out, int out_size) {
    const float* ev      = (const float*)d_in[0];
    // d_in[1] = src_mask (deterministic tril) — recomputed as j<=i
    const float* embed_w = (const float*)d_in[2];
    const float* q_w     = (const float*)d_in[3];
    const float* q_b     = (const float*)d_in[4];
    const float* k_w     = (const float*)d_in[5];
    const float* k_b     = (const float*)d_in[6];
    const float* v_w     = (const float*)d_in[7];
    const float* v_b     = (const float*)d_in[8];
    const float* alpha_w = (const float*)d_in[9];
    const float* alpha_b = (const float*)d_in[10];
    const float* gamma_w = (const float*)d_in[11];
    const float* gamma_b = (const float*)d_in[12];
    const float* mu_w    = (const float*)d_in[13];
    const float* mu_b    = (const float*)d_in[14];
    float* out = (float*)d_out;

    prep_kernel<<<128, 256>>>(ev, embed_w, q_w, q_b, k_w, k_b, v_w, v_b, alpha_w, gamma_w);
    attn_kernel<<<BB*HH*8, 256>>>();
    vmu_final<<<(BB*LL*DKK + 255)/256, 256>>>(mu_w, mu_b, out);
    big_kernel<<<512, 256>>>(alpha_b, gamma_b, out);
}